// round 3
// baseline (speedup 1.0000x reference)
#include <cuda_runtime.h>
#include <cuda_fp16.h>
#include <cstdint>
#include <cstddef>

#define N_NODES 8192
#define IN_F    256
#define OUT_F   128
#define ALPHA   0.2f

#define PW 72            // w tile row stride (halfs)  -> conflict-free frag loads
#define PK 72            // WhT tile row stride (halfs)

// ---------------- device scratch (no allocations allowed) ----------------
__device__ __align__(16) __half  g_WhT[(size_t)OUT_F * N_NODES]; // [n][j] = Wh[j][n], fp16
__device__ float  g_src[N_NODES];
__device__ float  g_dst[N_NODES];
__device__ __align__(16) float4 g_rowpack[N_NODES];  // (-s, exp(s-M), exp(a*s-M), 0)
__device__ __align__(16) float4 g_colpack[N_NODES];  // (d,  exp(d),   exp(a*d),   0)

// ============================================================================
// Kernel 1: Wh = h @ W (fp32 tiled SGEMM), emit WhT fp16 + src/dst vectors.
// Grid 128 x 256 thr, each CTA computes a 64x128 tile of Wh.
// ============================================================================
__global__ __launch_bounds__(256) void k1_wh(const float* __restrict__ h,
                                             const float* __restrict__ W,
                                             const float* __restrict__ a_vec) {
    __shared__ float As[32][68];     // [k][row] transposed h chunk
    __shared__ float Bs[32][132];    // [k][col] W chunk
    __shared__ __half ot[128][72];   // [col][row] fp16 output staging (for transposed write)
    __shared__ float src_s[64], dst_s[64];

    const int tid = threadIdx.x;
    const int tx = tid & 31;         // col group: 4 cols
    const int ty = tid >> 5;         // row group: 8 rows
    const int i0 = blockIdx.x * 64;

    if (tid < 64) { src_s[tid] = 0.f; dst_s[tid] = 0.f; }

    float acc[8][4];
#pragma unroll
    for (int r = 0; r < 8; ++r)
#pragma unroll
        for (int c = 0; c < 4; ++c) acc[r][c] = 0.f;

    for (int kb = 0; kb < IN_F; kb += 32) {
        __syncthreads();
        // load h tile 64 rows x 32 k  (transposed store)
#pragma unroll
        for (int c = 0; c < 2; ++c) {
            int idx = tid + c * 256;
            int r = idx >> 3, q = idx & 7;
            float4 v = *(const float4*)&h[(size_t)(i0 + r) * IN_F + kb + q * 4];
            As[q * 4 + 0][r] = v.x;
            As[q * 4 + 1][r] = v.y;
            As[q * 4 + 2][r] = v.z;
            As[q * 4 + 3][r] = v.w;
        }
        // load W tile 32 k x 128 cols
#pragma unroll
        for (int c = 0; c < 4; ++c) {
            int idx = tid + c * 256;
            int r = idx >> 5, q = idx & 31;
            *(float4*)&Bs[r][q * 4] = *(const float4*)&W[(size_t)(kb + r) * OUT_F + q * 4];
        }
        __syncthreads();
#pragma unroll
        for (int kk = 0; kk < 32; ++kk) {
            float4 b  = *(float4*)&Bs[kk][tx * 4];
            float4 a0 = *(float4*)&As[kk][ty * 8];
            float4 a1 = *(float4*)&As[kk][ty * 8 + 4];
            float ar[8] = {a0.x, a0.y, a0.z, a0.w, a1.x, a1.y, a1.z, a1.w};
            float bc[4] = {b.x, b.y, b.z, b.w};
#pragma unroll
            for (int r = 0; r < 8; ++r)
#pragma unroll
                for (int c = 0; c < 4; ++c) acc[r][c] += ar[r] * bc[c];
        }
    }
    __syncthreads();

    // src/dst partials (fp32)
    float a1v[4], a2v[4];
#pragma unroll
    for (int c = 0; c < 4; ++c) {
        a1v[c] = a_vec[tx * 4 + c];
        a2v[c] = a_vec[OUT_F + tx * 4 + c];
    }
#pragma unroll
    for (int r = 0; r < 8; ++r) {
        float s = 0.f, d = 0.f;
#pragma unroll
        for (int c = 0; c < 4; ++c) { s += acc[r][c] * a1v[c]; d += acc[r][c] * a2v[c]; }
        atomicAdd(&src_s[ty * 8 + r], s);
        atomicAdd(&dst_s[ty * 8 + r], d);
    }

    // fp16 staging, transposed: ot[col][row]
#pragma unroll
    for (int r = 0; r < 8; ++r)
#pragma unroll
        for (int c = 0; c < 4; ++c)
            ot[tx * 4 + c][ty * 8 + r] = __float2half_rn(acc[r][c]);
    __syncthreads();

    // coalesced write of WhT[n][i0..i0+63]
#pragma unroll
    for (int c = 0; c < 4; ++c) {
        int idx = tid + c * 256;
        int n = idx >> 3, seg = idx & 7;
        *(uint4*)&g_WhT[(size_t)n * N_NODES + i0 + seg * 8] = *(uint4*)&ot[n][seg * 8];
    }
    if (tid < 64) {
        g_src[i0 + tid] = src_s[tid];
        g_dst[i0 + tid] = dst_s[tid];
    }
}

// ============================================================================
// Kernel 2: global max(dst) + per-node exp tables. 1 block x 256 threads.
// ============================================================================
__global__ __launch_bounds__(256) void k2_params() {
    __shared__ float red[256];
    const int tid = threadIdx.x;
    float m = -1e30f;
    for (int i = tid; i < N_NODES; i += 256) m = fmaxf(m, g_dst[i]);
    red[tid] = m;
    __syncthreads();
    for (int s = 128; s > 0; s >>= 1) {
        if (tid < s) red[tid] = fmaxf(red[tid], red[tid + s]);
        __syncthreads();
    }
    const float Dmax = red[0];
    for (int i = tid; i < N_NODES; i += 256) {
        float s = g_src[i], d = g_dst[i];
        float t = s + Dmax;
        float M = (t >= 0.f) ? t : ALPHA * t;     // row scale: max possible e in row
        g_rowpack[i] = make_float4(-s, __expf(s - M), __expf(ALPHA * s - M), 0.f);
        g_colpack[i] = make_float4(d, __expf(d), __expf(ALPHA * d), 0.f);
    }
}

// ============================================================================
// Kernel 3: fused masked-softmax attention + attn@Wh + ELU.
// Grid 128 CTAs x 256 thr. CTA = 64 rows, loop j over 8192 in chunks of 64.
// ============================================================================
#define B_OFF   0
#define B_BYTES (2 * 128 * PK * 2)           // 73728
#define W_OFF   (B_OFF + B_BYTES)            // 73728
#define W_BYTES (2 * 64 * PW * 2)            // 36864
#define CP_OFF  (W_OFF + W_BYTES)            // 110592
#define CP_BYTES (2 * 64 * 16)               // 2048
#define RSP_OFF (CP_OFF + CP_BYTES)          // 112640
#define RSI_OFF (RSP_OFF + 4 * 64 * 4)       // 113664
#define SMEM3   (RSI_OFF + 64 * 4)           // 113920

__device__ __forceinline__ void cp16(void* dst_smem, const void* src) {
    uint32_t d = (uint32_t)__cvta_generic_to_shared(dst_smem);
    asm volatile("cp.async.cg.shared.global [%0], [%1], 16;" :: "r"(d), "l"(src) : "memory");
}
__device__ __forceinline__ void cp_commit() {
    asm volatile("cp.async.commit_group;" ::: "memory");
}
__device__ __forceinline__ void cp_wait0() {
    asm volatile("cp.async.wait_group 0;" ::: "memory");
}

__device__ __forceinline__ void mma16816(float* c, const uint32_t* a, uint32_t b0, uint32_t b1) {
    asm volatile(
        "mma.sync.aligned.m16n8k16.row.col.f32.f16.f16.f32 "
        "{%0,%1,%2,%3}, {%4,%5,%6,%7}, {%8,%9}, {%0,%1,%2,%3};"
        : "+f"(c[0]), "+f"(c[1]), "+f"(c[2]), "+f"(c[3])
        : "r"(a[0]), "r"(a[1]), "r"(a[2]), "r"(a[3]), "r"(b0), "r"(b1));
}

// issue async stages of WhT tile + colpack for chunk starting at j0 into buffer buf
__device__ __forceinline__ void stage_async(char* sm, int tid, int buf, int j0) {
    __half* b_s = (__half*)(sm + B_OFF);
#pragma unroll
    for (int c = 0; c < 4; ++c) {
        int idx = tid + c * 256;
        int n = idx >> 3, seg = idx & 7;
        cp16(&b_s[(size_t)(buf * 128 + n) * PK + seg * 8],
             &g_WhT[(size_t)n * N_NODES + j0 + seg * 8]);
    }
    if (tid < 64) {
        float4* cp_s = (float4*)(sm + CP_OFF);
        cp16(&cp_s[buf * 64 + tid], &g_colpack[j0 + tid]);
    }
}

// compute 16 attention weights of one row from adj regs + column tables, store fp16
__device__ __forceinline__ void wgen16(const int4* ar, const float4* cp, int jbase,
                                       float th, float E1, float E2,
                                       __half* wd, float& rsum) {
    __align__(16) __half hw[16];
#pragma unroll
    for (int q = 0; q < 4; ++q) {
        int4 v = ar[q];
        int vi[4] = {v.x, v.y, v.z, v.w};
#pragma unroll
        for (int e = 0; e < 4; ++e) {
            float4 c4 = cp[jbase + q * 4 + e];        // broadcast LDS.128
            bool pr = (c4.x >= th);                   // s_i + d_j >= 0
            float w = (vi[e] > 0) ? (pr ? E1 : E2) * (pr ? c4.y : c4.z) : 0.f;
            rsum += w;
            hw[q * 4 + e] = __float2half_rn(w);
        }
    }
    *(uint4*)wd       = *(uint4*)hw;
    *(uint4*)(wd + 8) = *(uint4*)(hw + 8);
}

__device__ __forceinline__ float elu1(float x) {
    return x > 0.f ? x : (__expf(x) - 1.f);
}

__global__ __launch_bounds__(256) void k3_attn(const int* __restrict__ adj,
                                               float* __restrict__ out) {
    extern __shared__ char sm[];
    __half* b_s   = (__half*)(sm + B_OFF);
    __half* w_s   = (__half*)(sm + W_OFF);
    float4* cp_s  = (float4*)(sm + CP_OFF);
    float*  rsp   = (float*)(sm + RSP_OFF);
    float*  rsi   = (float*)(sm + RSI_OFF);

    const int tid  = threadIdx.x;
    const int lane = tid & 31;
    const int warp = tid >> 5;
    const int i0   = blockIdx.x * 64;

    // ---- weight-gen identity: lane owns one row forever ----
    const int half_ = warp >> 2;               // 0: rows 0..31, 1: rows 32..63
    const int jgrp  = warp & 3;                // 16-wide j strip within chunk
    const int rloc  = half_ * 32 + lane;
    const float4 rp = g_rowpack[i0 + rloc];
    const float th = rp.x, E1 = rp.y, E2 = rp.z;
    float rsum = 0.f;
    const size_t adj_base = (size_t)(i0 + rloc) * N_NODES + jgrp * 16;

    // ---- mma identity: warp grid 2(m) x 4(n); warp = 32 rows x 32 cols ----
    const int wm = warp & 1, wn = warp >> 1;
    const int g  = lane >> 2, t4 = lane & 3;

    float acc[2][4][4];
#pragma unroll
    for (int mt = 0; mt < 2; ++mt)
#pragma unroll
        for (int nt = 0; nt < 4; ++nt)
#pragma unroll
            for (int e = 0; e < 4; ++e) acc[mt][nt][e] = 0.f;

    // ---- prologue: fill buffer 0 ----
    {
        stage_async(sm, tid, 0, 0);
        cp_commit();
        int4 ar[4];
        const int4* ap = (const int4*)(adj + adj_base);
#pragma unroll
        for (int q = 0; q < 4; ++q) ar[q] = ap[q];
        cp_wait0();
        __syncthreads();
        wgen16(ar, cp_s, jgrp * 16, th, E1, E2,
               w_s + (size_t)rloc * PW + jgrp * 16, rsum);
        __syncthreads();
    }

    // ---- main loop over 128 chunks of 64 columns ----
    for (int t = 0; t < N_NODES / 64; ++t) {
        const int cur = t & 1, nxt = cur ^ 1;
        const bool more = (t + 1 < N_NODES / 64);
        int4 ar[4];
        if (more) {
            const int j1 = (t + 1) * 64;
            stage_async(sm, tid, nxt, j1);
            cp_commit();
            const int4* ap = (const int4*)(adj + adj_base + j1);
#pragma unroll
            for (int q = 0; q < 4; ++q) ar[q] = ap[q];   // latency hidden by mma below
        }

        // mma phase on buffer cur
        const __half* wb = w_s + (size_t)cur * 64 * PW;
        const __half* bb = b_s + (size_t)cur * 128 * PK;
#pragma unroll
        for (int ks = 0; ks < 4; ++ks) {
            const int kof = ks * 16;
            uint32_t af[2][4];
#pragma unroll
            for (int mt = 0; mt < 2; ++mt) {
                const int r = wm * 32 + mt * 16;
                af[mt][0] = *(const uint32_t*)&wb[(r + g) * PW + kof + 2 * t4];
                af[mt][1] = *(const uint32_t*)&wb[(r + g + 8) * PW + kof + 2 * t4];
                af[mt][2] = *(const uint32_t*)&wb[(r + g) * PW + kof + 2 * t4 + 8];
                af[mt][3] = *(const uint32_t*)&wb[(r + g + 8) * PW + kof + 2 * t4 + 8];
            }
#pragma unroll
            for (int nt = 0; nt < 4; ++nt) {
                const int n = wn * 32 + nt * 8 + g;
                uint32_t b0 = *(const uint32_t*)&bb[n * PK + kof + 2 * t4];
                uint32_t b1 = *(const uint32_t*)&bb[n * PK + kof + 2 * t4 + 8];
                mma16816(acc[0][nt], af[0], b0, b1);
                mma16816(acc[1][nt], af[1], b0, b1);
            }
        }

        if (more) {
            cp_wait0();
            __syncthreads();   // colpack[nxt] visible to all lanes
            wgen16(ar, cp_s + nxt * 64, jgrp * 16, th, E1, E2,
                   w_s + (size_t)nxt * 64 * PW + (size_t)rloc * PW + jgrp * 16, rsum);
        }
        __syncthreads();       // w[nxt]/b[nxt] ready; w[cur] free to be overwritten later
    }

    // ---- row-sum reduction across the 4 j-strip warps ----
    rsp[jgrp * 64 + rloc] = rsum;
    __syncthreads();
    if (tid < 64) {
        float s = rsp[tid] + rsp[64 + tid] + rsp[128 + tid] + rsp[192 + tid];
        rsi[tid] = 1.f / s;
    }
    __syncthreads();

    // ---- epilogue: normalize + ELU + store ----
#pragma unroll
    for (int mt = 0; mt < 2; ++mt) {
        const int r = wm * 32 + mt * 16 + g;
        const float i1 = rsi[r], i2 = rsi[r + 8];
#pragma unroll
        for (int nt = 0; nt < 4; ++nt) {
            const int col = wn * 32 + nt * 8 + 2 * t4;
            float2 o1, o2;
            o1.x = elu1(acc[mt][nt][0] * i1);
            o1.y = elu1(acc[mt][nt][1] * i1);
            o2.x = elu1(acc[mt][nt][2] * i2);
            o2.y = elu1(acc[mt][nt][3] * i2);
            *(float2*)&out[(size_t)(i0 + r) * OUT_F + col] = o1;
            *(float2*)&out[(size_t)(i0 + r + 8) * OUT_F + col] = o2;
        }
    }
}

// ============================================================================
extern "C" void kernel_launch(void* const* d_in, const int* in_sizes, int n_in,
                              void* d_out, int out_size) {
    const float* h   = (const float*)d_in[0];
    const int*   adj = (const int*)d_in[1];
    const float* W   = (const float*)d_in[2];
    const float* a   = (const float*)d_in[3];
    float* out = (float*)d_out;

    (void)in_sizes; (void)n_in; (void)out_size;

    cudaFuncSetAttribute(k3_attn, cudaFuncAttributeMaxDynamicSharedMemorySize, SMEM3);

    k1_wh<<<N_NODES / 64, 256>>>(h, W, a);
    k2_params<<<1, 256>>>();
    k3_attn<<<N_NODES / 64, 256, SMEM3>>>(adj, out);
}

// round 6
// speedup vs baseline: 2.6527x; 2.6527x over previous
#include <cuda_runtime.h>
#include <cuda_fp16.h>
#include <cstdint>
#include <cstddef>

#define N_NODES 8192
#define IN_F    256
#define OUT_F   128
#define ALPHA   0.2f
#define NSPLIT  4
#define JCOLS   (N_NODES / NSPLIT)     // 2048 cols per CTA
#define NC      (JCOLS / 64)           // 32 chunks

// ---------------- device scratch (no allocations allowed) ----------------
__device__ __align__(16) __half  g_WhT[(size_t)OUT_F * N_NODES]; // [n][j] = Wh[j][n]
__device__ float  g_src[N_NODES];
__device__ float  g_dst[N_NODES];
__device__ __align__(16) float4 g_rowpack[N_NODES];  // (-s, exp(s-M), exp(a*s-M), 0)
__device__ __align__(16) float4 g_colpack[N_NODES];  // (d,  exp(d),   exp(a*d),   0)
__device__ __align__(16) float  g_part[(size_t)NSPLIT * N_NODES * OUT_F];
__device__ float  g_rsum[NSPLIT * N_NODES];

// ============================================================================
// Kernel 1: Wh = h @ W (fp32 SGEMM, 32-row tiles, 256 CTAs), emit WhT fp16 +
// src/dst via warp shfl reductions.
// ============================================================================
__global__ __launch_bounds__(256) void k1_wh(const float* __restrict__ h,
                                             const float* __restrict__ W,
                                             const float* __restrict__ a_vec) {
    __shared__ float As[32][36];     // [k][row]
    __shared__ float Bs[32][132];    // [k][col]
    __shared__ __half ot[128][40];   // [col][row] staging for transposed write
    __shared__ float srd[64];        // src[0..31], dst[32..63]

    const int tid = threadIdx.x;
    const int tx = tid & 31;         // col group (4 cols)
    const int ty = tid >> 5;         // row group (4 rows)
    const int i0 = blockIdx.x * 32;

    float acc[4][4];
#pragma unroll
    for (int r = 0; r < 4; ++r)
#pragma unroll
        for (int c = 0; c < 4; ++c) acc[r][c] = 0.f;

    for (int kb = 0; kb < IN_F; kb += 32) {
        __syncthreads();
        {   // h tile: 32 rows x 32 k, transposed store (1 float4/thread)
            int r = tid >> 3, q = tid & 7;
            float4 v = *(const float4*)&h[(size_t)(i0 + r) * IN_F + kb + q * 4];
            As[q * 4 + 0][r] = v.x;
            As[q * 4 + 1][r] = v.y;
            As[q * 4 + 2][r] = v.z;
            As[q * 4 + 3][r] = v.w;
        }
#pragma unroll
        for (int c = 0; c < 4; ++c) {   // W tile 32 k x 128 cols
            int idx = tid + c * 256;
            int r = idx >> 5, q = idx & 31;
            *(float4*)&Bs[r][q * 4] = *(const float4*)&W[(size_t)(kb + r) * OUT_F + q * 4];
        }
        __syncthreads();
#pragma unroll
        for (int kk = 0; kk < 32; ++kk) {
            float4 b = *(float4*)&Bs[kk][tx * 4];
            float ar[4] = {As[kk][ty * 4], As[kk][ty * 4 + 1],
                           As[kk][ty * 4 + 2], As[kk][ty * 4 + 3]};
            float bc[4] = {b.x, b.y, b.z, b.w};
#pragma unroll
            for (int r = 0; r < 4; ++r)
#pragma unroll
                for (int c = 0; c < 4; ++c) acc[r][c] += ar[r] * bc[c];
        }
    }
    __syncthreads();

    // src/dst: each warp owns 4 full rows -> shfl reduce across 32 lanes (cols)
    float a1v[4], a2v[4];
#pragma unroll
    for (int c = 0; c < 4; ++c) {
        a1v[c] = a_vec[tx * 4 + c];
        a2v[c] = a_vec[OUT_F + tx * 4 + c];
    }
#pragma unroll
    for (int r = 0; r < 4; ++r) {
        float s = 0.f, d = 0.f;
#pragma unroll
        for (int c = 0; c < 4; ++c) { s += acc[r][c] * a1v[c]; d += acc[r][c] * a2v[c]; }
#pragma unroll
        for (int off = 16; off > 0; off >>= 1) {
            s += __shfl_xor_sync(0xffffffffu, s, off);
            d += __shfl_xor_sync(0xffffffffu, d, off);
        }
        if (tx == 0) { srd[ty * 4 + r] = s; srd[32 + ty * 4 + r] = d; }
    }

    // fp16 transpose staging
#pragma unroll
    for (int r = 0; r < 4; ++r)
#pragma unroll
        for (int c = 0; c < 4; ++c)
            ot[tx * 4 + c][ty * 4 + r] = __float2half_rn(acc[r][c]);
    __syncthreads();

    // write WhT[n][i0..i0+31]
#pragma unroll
    for (int c = 0; c < 2; ++c) {
        int idx = tid + c * 256;
        int n = idx >> 2, seg = idx & 3;
        *(uint4*)&g_WhT[(size_t)n * N_NODES + i0 + seg * 8] = *(uint4*)&ot[n][seg * 8];
    }
    if (tid < 32) {
        g_src[i0 + tid] = srd[tid];
        g_dst[i0 + tid] = srd[32 + tid];
    }
}

// ============================================================================
// Kernel 2: global max(dst) + per-node exp tables. 1 block x 256 threads.
// ============================================================================
__global__ __launch_bounds__(256) void k2_params() {
    __shared__ float red[256];
    const int tid = threadIdx.x;
    float m = -1e30f;
    for (int i = tid; i < N_NODES; i += 256) m = fmaxf(m, g_dst[i]);
    red[tid] = m;
    __syncthreads();
    for (int s = 128; s > 0; s >>= 1) {
        if (tid < s) red[tid] = fmaxf(red[tid], red[tid + s]);
        __syncthreads();
    }
    const float Dmax = red[0];
    for (int i = tid; i < N_NODES; i += 256) {
        float s = g_src[i], d = g_dst[i];
        float t = s + Dmax;
        float M = (t >= 0.f) ? t : ALPHA * t;     // upper bound of e over the row
        g_rowpack[i] = make_float4(-s, __expf(s - M), __expf(ALPHA * s - M), 0.f);
        g_colpack[i] = make_float4(d, __expf(d), __expf(ALPHA * d), 0.f);
    }
}

// ============================================================================
// Kernel 3: fused masked-softmax weights + HMMA (mma.sync) attention GEMM.
// Grid 256 CTAs (64 row-tiles x 4 j-splits) x 512 thr.
// CTA = 128 rows x 2048 cols, chunks of 64 cols, double buffered smem.
// ============================================================================
#define A_OFF   0                        // w tiles: 2 x 128 x 128B = 32KB
#define B_OFF   32768                    // WhT tiles: 2 x 128 x 128B = 32KB
#define ADJ_OFF 65536                    // adj tiles: 2 x 128 x 256B = 64KB
#define CP_OFF  131072                   // colpack: 2 x 64 x 16B = 2KB
#define RP_OFF  133120                   // rowpack: 128 x 16B = 2KB
#define RSP_OFF 135168                   // row sums: 128 x 4B
#define SMEM3   135680

#define CPWAIT1() asm volatile("cp.async.wait_group 1;" ::: "memory")
#define CPWAIT0() asm volatile("cp.async.wait_group 0;" ::: "memory")

__device__ __forceinline__ void cp16(uint32_t dst, const void* src) {
    asm volatile("cp.async.cg.shared.global [%0], [%1], 16;" :: "r"(dst), "l"(src) : "memory");
}
__device__ __forceinline__ void ldsm4(uint32_t& r0, uint32_t& r1, uint32_t& r2, uint32_t& r3,
                                      uint32_t addr) {
    asm volatile("ldmatrix.sync.aligned.m8n8.x4.shared.b16 {%0,%1,%2,%3}, [%4];"
                 : "=r"(r0), "=r"(r1), "=r"(r2), "=r"(r3) : "r"(addr));
}
__device__ __forceinline__ void mma16816(float* c, const uint32_t* a, uint32_t b0, uint32_t b1) {
    asm volatile(
        "mma.sync.aligned.m16n8k16.row.col.f32.f16.f16.f32 "
        "{%0,%1,%2,%3}, {%4,%5,%6,%7}, {%8,%9}, {%0,%1,%2,%3};"
        : "+f"(c[0]), "+f"(c[1]), "+f"(c[2]), "+f"(c[3])
        : "r"(a[0]), "r"(a[1]), "r"(a[2]), "r"(a[3]), "r"(b0), "r"(b1));
}

// stage chunk (64 cols) into buffer buf. group1 = colpack+adj, group2 = B.
__device__ __forceinline__ void stage(uint32_t smu, int tid, int buf,
                                      const int* adj, int i0, size_t j0) {
    if (tid < 64)
        cp16(smu + CP_OFF + buf * 1024 + tid * 16, &g_colpack[j0 + tid]);
#pragma unroll
    for (int c = 0; c < 4; ++c) {
        int idx = tid + c * 512;
        int row = idx >> 4, s = idx & 15;
        cp16(smu + ADJ_OFF + buf * 32768 + row * 256 + s * 16,
             adj + (size_t)(i0 + row) * N_NODES + j0 + s * 4);
    }
    asm volatile("cp.async.commit_group;" ::: "memory");
#pragma unroll
    for (int c = 0; c < 2; ++c) {
        int idx = tid + c * 512;
        int n = idx >> 3, chn = idx & 7;
        cp16(smu + B_OFF + buf * 16384 + n * 128 + ((chn ^ (n & 7)) << 4),
             &g_WhT[(size_t)n * N_NODES + j0 + chn * 8]);
    }
    asm volatile("cp.async.commit_group;" ::: "memory");
}

// weight-gen: thread owns one column (of 64) x 16 rows. Reads adj+colpack smem,
// writes fp16 weights to swizzled A tile.
__device__ __forceinline__ void wgen(char* sm, int buf, int rg, int col) {
    const float4 c4 = *(const float4*)(sm + CP_OFF + buf * 1024 + col * 16);
    const char* ab = sm + ADJ_OFF + buf * 32768 + col * 4;
    const float4* rps = (const float4*)(sm + RP_OFF);
    char* aw = sm + A_OFF + buf * 16384 + ((col & 7) * 2) + 0;
    const int segc = col >> 3;
    int av[16];
#pragma unroll
    for (int r = 0; r < 16; ++r)
        av[r] = *(const int*)(ab + (rg * 16 + r) * 256);
#pragma unroll
    for (int r = 0; r < 16; ++r) {
        const int row = rg * 16 + r;
        const float4 rp = rps[row];                         // broadcast LDS
        float wv = (c4.x >= rp.x) ? rp.y * c4.y : rp.z * c4.z;
        wv = (av[r] > 0) ? wv : 0.f;
        *(__half*)(aw + row * 128 + ((segc ^ (row & 7)) << 4)) = __float2half_rn(wv);
    }
}

__global__ __launch_bounds__(512, 1) void k3_attn(const int* __restrict__ adj) {
    extern __shared__ char sm[];
    const uint32_t smu = (uint32_t)__cvta_generic_to_shared(sm);
    const int tid = threadIdx.x, lane = tid & 31, warp = tid >> 5;
    const int split = blockIdx.x & 3;
    const int i0 = (blockIdx.x >> 2) * 128;
    const size_t jbase = (size_t)split * JCOLS;

    // wgen identity
    const int rg = warp >> 1;                       // 8 row groups of 16
    const int col = (warp & 1) * 32 + lane;         // column within chunk
    // mma identity: 4(m) x 4(n) warps, each 32x32 out tile
    const int wm = warp & 3, wn = warp >> 2;
    const int g = lane >> 2, t4 = lane & 3;
    // ldmatrix lane addressing
    const int lrA = (lane & 7) + ((lane >> 3) & 1) * 8;   // A: row-in-16
    const int lkA = lane >> 4;                            // A: k-seg select
    const int lrB = (lane & 7) + ((lane >> 4) << 3);      // B: n-row-in-16
    const int lkB = (lane >> 3) & 1;                      // B: k-seg select
    const uint32_t bo = (g == 0) ? 0x3C003C00u : 0u;      // ones B frag (n==0)

    float acc[2][4][4];
    float accO[2][4];
#pragma unroll
    for (int mt = 0; mt < 2; ++mt) {
#pragma unroll
        for (int nt = 0; nt < 4; ++nt)
#pragma unroll
            for (int e = 0; e < 4; ++e) acc[mt][nt][e] = 0.f;
#pragma unroll
        for (int e = 0; e < 4; ++e) accO[mt][e] = 0.f;
    }

    // ---- prologue ----
    stage(smu, tid, 0, adj, i0, jbase);
    if (tid < 128)
        *(float4*)(sm + RP_OFF + tid * 16) = *(const float4*)&g_rowpack[i0 + tid];
    CPWAIT1();
    __syncthreads();
    wgen(sm, 0, rg, col);
    CPWAIT0();
    __syncthreads();

    // ---- main loop ----
    for (int t = 0; t < NC; ++t) {
        const int cur = t & 1, nxt = cur ^ 1;
        const bool more = (t + 1 < NC);
        if (more) stage(smu, tid, nxt, adj, i0, jbase + (size_t)(t + 1) * 64);

        // MMA on buffer cur
        {
            const uint32_t aB = smu + A_OFF + cur * 16384;
            const uint32_t bB = smu + B_OFF + cur * 16384;
#pragma unroll
            for (int ks = 0; ks < 4; ++ks) {
                uint32_t a[2][4], b[2][4];
#pragma unroll
                for (int mt = 0; mt < 2; ++mt) {
                    const int row = wm * 32 + mt * 16 + lrA;
                    const int seg = 2 * ks + lkA;
                    ldsm4(a[mt][0], a[mt][1], a[mt][2], a[mt][3],
                          aB + row * 128 + ((seg ^ (row & 7)) << 4));
                }
#pragma unroll
                for (int np = 0; np < 2; ++np) {
                    const int nr = wn * 32 + np * 16 + lrB;
                    const int seg = 2 * ks + lkB;
                    ldsm4(b[np][0], b[np][1], b[np][2], b[np][3],
                          bB + nr * 128 + ((seg ^ (nr & 7)) << 4));
                }
#pragma unroll
                for (int mt = 0; mt < 2; ++mt) {
#pragma unroll
                    for (int np = 0; np < 2; ++np) {
                        mma16816(acc[mt][np * 2],     a[mt], b[np][0], b[np][1]);
                        mma16816(acc[mt][np * 2 + 1], a[mt], b[np][2], b[np][3]);
                    }
                    if (wn == 0) mma16816(accO[mt], a[mt], bo, bo);
                }
            }
        }

        if (more) {
            CPWAIT1();             // colpack+adj(t+1) done
            __syncthreads();       // also: all mma(t-1) reads done before A[nxt] overwrite
            wgen(sm, nxt, rg, col);
            CPWAIT0();             // B(t+1) done
        }
        __syncthreads();
    }

    // ---- epilogue: partial outputs + row sums ----
    {
        float* pp = g_part + (size_t)split * N_NODES * OUT_F;
#pragma unroll
        for (int mt = 0; mt < 2; ++mt) {
            const int row = i0 + wm * 32 + mt * 16 + g;
#pragma unroll
            for (int nt = 0; nt < 4; ++nt) {
                const int cc = wn * 32 + nt * 8 + 2 * t4;
                *(float2*)&pp[(size_t)row * OUT_F + cc] =
                    make_float2(acc[mt][nt][0], acc[mt][nt][1]);
                *(float2*)&pp[(size_t)(row + 8) * OUT_F + cc] =
                    make_float2(acc[mt][nt][2], acc[mt][nt][3]);
            }
        }
    }
    float* rsp = (float*)(sm + RSP_OFF);
    if (wn == 0 && t4 == 0) {
#pragma unroll
        for (int mt = 0; mt < 2; ++mt) {
            rsp[wm * 32 + mt * 16 + g]     = accO[mt][0];
            rsp[wm * 32 + mt * 16 + g + 8] = accO[mt][2];
        }
    }
    __syncthreads();
    if (tid < 128) g_rsum[split * N_NODES + i0 + tid] = rsp[tid];
}

// ============================================================================
// Kernel 4: combine 4 split partials, normalize, ELU, store.
// ============================================================================
__device__ __forceinline__ float elu1(float x) {
    return x > 0.f ? x : (__expf(x) - 1.f);
}

__global__ __launch_bounds__(256) void k4_fin(float* __restrict__ out) {
    int gi = blockIdx.x * 256 + threadIdx.x;      // 65536 threads, 16 floats each
    int row = gi >> 3;
    int cof = (gi & 7) * 16;
    float s = 0.f;
#pragma unroll
    for (int p = 0; p < NSPLIT; ++p) s += g_rsum[p * N_NODES + row];
    float rinv = 1.f / s;
    float* op = out + (size_t)row * OUT_F + cof;
    const float* pb = g_part + (size_t)row * OUT_F + cof;
#pragma unroll
    for (int c = 0; c < 4; ++c) {
        float4 a = *(const float4*)(pb + c * 4);
#pragma unroll
        for (int p = 1; p < NSPLIT; ++p) {
            float4 b = *(const float4*)(pb + (size_t)p * N_NODES * OUT_F + c * 4);
            a.x += b.x; a.y += b.y; a.z += b.z; a.w += b.w;
        }
        float4 o;
        o.x = elu1(a.x * rinv);
        o.y = elu1(a.y * rinv);
        o.z = elu1(a.z * rinv);
        o.w = elu1(a.w * rinv);
        *(float4*)(op + c * 4) = o;
    }
}

// ============================================================================
extern "C" void kernel_launch(void* const* d_in, const int* in_sizes, int n_in,
                              void* d_out, int out_size) {
    const float* h   = (const float*)d_in[0];
    const int*   adj = (const int*)d_in[1];
    const float* W   = (const float*)d_in[2];
    const float* a   = (const float*)d_in[3];
    float* out = (float*)d_out;
    (void)in_sizes; (void)n_in; (void)out_size;

    cudaFuncSetAttribute(k3_attn, cudaFuncAttributeMaxDynamicSharedMemorySize, SMEM3);

    k1_wh<<<N_NODES / 32, 256>>>(h, W, a);
    k2_params<<<1, 256>>>();
    k3_attn<<<N_NODES / 128 * NSPLIT, 512, SMEM3>>>(adj);
    k4_fin<<<(N_NODES * OUT_F) / (16 * 256), 256>>>(out);
}